// round 3
// baseline (speedup 1.0000x reference)
#include <cuda_runtime.h>

// PointerNet_30949534335591 — R3 (stability re-bench of the R2 winner)
//
// Mathematical identity (proven R1/R2, rel_err = 0.0 exact): the decoder's
// argmax is over a length-1 axis -> identically 0; the output is a constant
// zero [B, S] int32 tensor and the entire LSTM stack is dead code w.r.t. it.
//
// Performance model: 512 KB of stores = ~0.06us of HBM time vs ~5us measured
// -> >98% of dur_us is fixed per-replay overhead (cudaGraphLaunch + single-
// node launch-to-complete latency). The minimal graph is exactly ONE memset
// node, which R2 measured 0.73us cheaper than a kernel node (5.06 vs 5.79).
// This round re-benches that configuration to pin the noise band; no cheaper
// node type exists, so if stable this is the floor.

extern "C" void kernel_launch(void* const* d_in, const int* in_sizes, int n_in,
                              void* d_out, int out_size) {
    (void)d_in; (void)in_sizes; (void)n_in;
    // Captured as a single CUDA-graph memset node: zero B*S int32 elements.
    cudaMemsetAsync(d_out, 0, (size_t)out_size * sizeof(int), 0);
}